// round 2
// baseline (speedup 1.0000x reference)
#include <cuda_runtime.h>
#include <cuda_bf16.h>
#include <cstdint>

// Problem dims
#define T_ITER 8
#define L_DIM  4096
#define D_DIM  512
#define H_DIM  256
#define M_TOT  (T_ITER * L_DIM)   // 32768 flattened (t, l) rows

// ---------------- scratch (static __device__, no allocation) ----------------
__device__ float          g_E[(size_t)M_TOT * H_DIM];   // E[t*L+l][j] = emb @ Ws (raw, no bias)  ~32 MB
__device__ float          g_dxyz[(size_t)M_TOT * 3];    // row dots with Wx/Wy/Wz
__device__ __nv_bfloat16  g_BThi[H_DIM * D_DIM];        // Ws^T split-hi, layout [n][k]
__device__ __nv_bfloat16  g_BTlo[H_DIM * D_DIM];        // Ws^T split-lo, layout [n][k]

// ---------------- kernel 0: split Ws into bf16 hi/lo, transposed ----------------
__global__ void k_convert_ws(const float* __restrict__ Ws) {
    int idx = blockIdx.x * blockDim.x + threadIdx.x;   // 512*256 threads exactly
    float v = Ws[idx];
    int k = idx >> 8;        // row in Ws (K)
    int n = idx & 255;       // col in Ws (N)
    __nv_bfloat16 h = __float2bfloat16(v);
    __nv_bfloat16 l = __float2bfloat16(v - __bfloat162float(h));
    g_BThi[n * D_DIM + k] = h;
    g_BTlo[n * D_DIM + k] = l;
}

// ---------------- kernel 1: E = emb_flat @ Ws via bf16x3 mma.sync ----------------
#define BM 128
#define BN 128
#define BK 32
#define SAS 40   // smem row stride (bf16 elems): 32 data + 8 pad -> conflict-free frag reads

__device__ __forceinline__ void mma_bf16(float c[4],
                                         uint32_t a0, uint32_t a1, uint32_t a2, uint32_t a3,
                                         uint32_t b0, uint32_t b1) {
    asm volatile(
        "mma.sync.aligned.m16n8k16.row.col.f32.bf16.bf16.f32 "
        "{%0,%1,%2,%3}, {%4,%5,%6,%7}, {%8,%9}, {%0,%1,%2,%3};\n"
        : "+f"(c[0]), "+f"(c[1]), "+f"(c[2]), "+f"(c[3])
        : "r"(a0), "r"(a1), "r"(a2), "r"(a3), "r"(b0), "r"(b1));
}

__global__ void __launch_bounds__(256, 2) k_gemm_e(const float* __restrict__ A) {
    __shared__ __align__(16) __nv_bfloat16 sAh[BM * SAS];
    __shared__ __align__(16) __nv_bfloat16 sAl[BM * SAS];
    __shared__ __align__(16) __nv_bfloat16 sBh[BN * SAS];
    __shared__ __align__(16) __nv_bfloat16 sBl[BN * SAS];

    const int tid  = threadIdx.x;
    const int lane = tid & 31, wid = tid >> 5;
    const int grp  = lane >> 2, tig = lane & 3;
    const int m0   = blockIdx.x * BM, n0 = blockIdx.y * BN;
    const int wm   = (wid & 1) * 64;     // warp M offset (2 warps in M)
    const int wn   = (wid >> 1) * 32;    // warp N offset (4 warps in N)

    // global->reg staging assignments
    const int arow = tid >> 3;               // 0..31 (x4 passes -> 128 rows)
    const int af4  = (tid & 7) * 4;          // float4 column within BK
    const int bn   = tid >> 1;               // 0..127 B row (n)
    const int bk   = (tid & 1) * 16;         // 16-elem half of BK

    float acc[4][4][4];
    #pragma unroll
    for (int i = 0; i < 4; i++)
        #pragma unroll
        for (int j = 0; j < 4; j++)
            #pragma unroll
            for (int r = 0; r < 4; r++) acc[i][j][r] = 0.f;

    float4 aReg[4];
    uint4  bhReg0, bhReg1, blReg0, blReg1;

    const float* Abase = A + (size_t)m0 * D_DIM;
    const __nv_bfloat16* Bh = g_BThi + (size_t)(n0 + bn) * D_DIM + bk;
    const __nv_bfloat16* Bl = g_BTlo + (size_t)(n0 + bn) * D_DIM + bk;

    // prologue loads (kt = 0)
    #pragma unroll
    for (int p = 0; p < 4; p++)
        aReg[p] = *(const float4*)(Abase + (size_t)(p * 32 + arow) * D_DIM + af4);
    bhReg0 = *(const uint4*)(Bh);     bhReg1 = *(const uint4*)(Bh + 8);
    blReg0 = *(const uint4*)(Bl);     blReg1 = *(const uint4*)(Bl + 8);

    for (int kt = 0; kt < D_DIM / BK; kt++) {
        // stage regs -> smem (convert A fp32 -> bf16 hi/lo on the fly)
        #pragma unroll
        for (int p = 0; p < 4; p++) {
            float f[4] = {aReg[p].x, aReg[p].y, aReg[p].z, aReg[p].w};
            unsigned short h[4], lo[4];
            #pragma unroll
            for (int q = 0; q < 4; q++) {
                __nv_bfloat16 hb = __float2bfloat16(f[q]);
                __nv_bfloat16 lb = __float2bfloat16(f[q] - __bfloat162float(hb));
                h[q]  = __bfloat16_as_ushort(hb);
                lo[q] = __bfloat16_as_ushort(lb);
            }
            int off = (p * 32 + arow) * SAS + af4;
            *(uint2*)&sAh[off] = make_uint2((uint32_t)h[0]  | ((uint32_t)h[1]  << 16),
                                            (uint32_t)h[2]  | ((uint32_t)h[3]  << 16));
            *(uint2*)&sAl[off] = make_uint2((uint32_t)lo[0] | ((uint32_t)lo[1] << 16),
                                            (uint32_t)lo[2] | ((uint32_t)lo[3] << 16));
        }
        {
            int off = bn * SAS + bk;
            *(uint4*)&sBh[off]     = bhReg0;  *(uint4*)&sBh[off + 8] = bhReg1;
            *(uint4*)&sBl[off]     = blReg0;  *(uint4*)&sBl[off + 8] = blReg1;
        }
        __syncthreads();

        // prefetch next tile into regs (overlaps with mma below)
        if (kt + 1 < D_DIM / BK) {
            const float* An = Abase + (kt + 1) * BK;
            #pragma unroll
            for (int p = 0; p < 4; p++)
                aReg[p] = *(const float4*)(An + (size_t)(p * 32 + arow) * D_DIM + af4);
            const __nv_bfloat16* Bh2 = Bh + (kt + 1) * BK;
            const __nv_bfloat16* Bl2 = Bl + (kt + 1) * BK;
            bhReg0 = *(const uint4*)(Bh2);  bhReg1 = *(const uint4*)(Bh2 + 8);
            blReg0 = *(const uint4*)(Bl2);  blReg1 = *(const uint4*)(Bl2 + 8);
        }

        #pragma unroll
        for (int ks = 0; ks < 2; ks++) {
            uint32_t bh[4][2], bl[4][2];
            #pragma unroll
            for (int ni = 0; ni < 4; ni++) {
                int r = wn + ni * 8 + grp;
                int c = ks * 16 + 2 * tig;
                bh[ni][0] = *(const uint32_t*)&sBh[r * SAS + c];
                bh[ni][1] = *(const uint32_t*)&sBh[r * SAS + c + 8];
                bl[ni][0] = *(const uint32_t*)&sBl[r * SAS + c];
                bl[ni][1] = *(const uint32_t*)&sBl[r * SAS + c + 8];
            }
            #pragma unroll
            for (int mi = 0; mi < 4; mi++) {
                int r = wm + mi * 16 + grp;
                int c = ks * 16 + 2 * tig;
                uint32_t ah0 = *(const uint32_t*)&sAh[r * SAS + c];
                uint32_t ah1 = *(const uint32_t*)&sAh[(r + 8) * SAS + c];
                uint32_t ah2 = *(const uint32_t*)&sAh[r * SAS + c + 8];
                uint32_t ah3 = *(const uint32_t*)&sAh[(r + 8) * SAS + c + 8];
                uint32_t al0 = *(const uint32_t*)&sAl[r * SAS + c];
                uint32_t al1 = *(const uint32_t*)&sAl[(r + 8) * SAS + c];
                uint32_t al2 = *(const uint32_t*)&sAl[r * SAS + c + 8];
                uint32_t al3 = *(const uint32_t*)&sAl[(r + 8) * SAS + c + 8];
                #pragma unroll
                for (int ni = 0; ni < 4; ni++) {
                    mma_bf16(acc[mi][ni], ah0, ah1, ah2, ah3, bh[ni][0], bh[ni][1]);  // hi*hi
                    mma_bf16(acc[mi][ni], ah0, ah1, ah2, ah3, bl[ni][0], bl[ni][1]);  // hi*lo
                    mma_bf16(acc[mi][ni], al0, al1, al2, al3, bh[ni][0], bh[ni][1]);  // lo*hi
                }
            }
        }
        __syncthreads();
    }

    // epilogue: fp32 accumulators -> g_E
    #pragma unroll
    for (int mi = 0; mi < 4; mi++) {
        #pragma unroll
        for (int ni = 0; ni < 4; ni++) {
            int row = m0 + wm + mi * 16 + grp;
            int col = n0 + wn + ni * 8 + 2 * tig;
            *(float2*)&g_E[(size_t)row * H_DIM + col]       = make_float2(acc[mi][ni][0], acc[mi][ni][1]);
            *(float2*)&g_E[(size_t)(row + 8) * H_DIM + col] = make_float2(acc[mi][ni][2], acc[mi][ni][3]);
        }
    }
}

// ---------------- kernel 2: dec row-dots dx/dy/dz for every (t, l) ----------------
__global__ void k_dec_dots(const float* __restrict__ emb, const float* __restrict__ Wx,
                           const float* __restrict__ Wy,  const float* __restrict__ Wz) {
    __shared__ float swx[D_DIM], swy[D_DIM], swz[D_DIM];
    int l = blockIdx.x;
    int tid = threadIdx.x, lane = tid & 31, t = tid >> 5;   // 8 warps = 8 time steps
    for (int i = tid; i < D_DIM; i += 256) {
        swx[i] = Wx[(size_t)l * D_DIM + i];
        swy[i] = Wy[(size_t)l * D_DIM + i];
        swz[i] = Wz[(size_t)l * D_DIM + i];
    }
    __syncthreads();
    const float* e = emb + ((size_t)t * L_DIM + l) * D_DIM;
    float sx = 0.f, sy = 0.f, sz = 0.f;
    #pragma unroll
    for (int i = lane; i < D_DIM; i += 32) {
        float v = e[i];
        sx += v * swx[i]; sy += v * swy[i]; sz += v * swz[i];
    }
    #pragma unroll
    for (int o = 16; o > 0; o >>= 1) {
        sx += __shfl_xor_sync(0xffffffffu, sx, o);
        sy += __shfl_xor_sync(0xffffffffu, sy, o);
        sz += __shfl_xor_sync(0xffffffffu, sz, o);
    }
    if (lane == 0) {
        size_t r = (size_t)t * L_DIM + l;
        g_dxyz[r * 3 + 0] = sx;
        g_dxyz[r * 3 + 1] = sy;
        g_dxyz[r * 3 + 2] = sz;
    }
}

// ---------------- kernel 3: fused 7-step recurrence, one warp per row ----------------
__device__ __forceinline__ float tanh_fast(float x) {
    float e = __expf(2.0f * x);              // large |x| saturates cleanly to +/-1
    return 1.0f - 2.0f / (e + 1.0f);
}

__global__ void k_seq(const float* __restrict__ rois, const float* __restrict__ Wh,
                      const float* __restrict__ bs,   const float* __restrict__ bx,
                      const float* __restrict__ by,   const float* __restrict__ bz,
                      float* __restrict__ out) {
    int wid = threadIdx.x >> 5, lane = threadIdx.x & 31;
    int l = blockIdx.x * 8 + wid;

    float wh[8], bsr[8], S[8];
    #pragma unroll
    for (int i = 0; i < 8; i++) {
        int j = i * 32 + lane;
        wh[i]  = Wh[(size_t)l * H_DIM + j];
        bsr[i] = bs[j];
        S[i]   = g_E[(size_t)l * H_DIM + j];   // t=0 rows: S_0 = emb0 @ Ws
    }
    float X = g_dxyz[(size_t)l * 3 + 0];
    float Y = g_dxyz[(size_t)l * 3 + 1];
    float Z = g_dxyz[(size_t)l * 3 + 2];
    float cx = rois[(size_t)l * 3 + 0];
    float cy = rois[(size_t)l * 3 + 1];
    float cz = rois[(size_t)l * 3 + 2];
    float bxl = bx[l], byl = by[l], bzl = bz[l];
    const float s0 = 1.0f / 767.0f, s2 = 1.0f / 575.0f;

    float px = (X + bxl) * s0 + cx;
    float py = (Y + byl) * s0 + cy;
    float pz = (Z + bzl) * s2 + cz;
    if (lane == 0) {
        out[(size_t)l * 3 + 0] = px;
        out[(size_t)l * 3 + 1] = py;
        out[(size_t)l * 3 + 2] = pz;
    }

    for (int t = 1; t < T_ITER; t++) {
        size_t r = (size_t)t * L_DIM + l;
        const float* Et = g_E + r * H_DIM;
        float e[8];
        float pf = 0.f, pa = 0.f;
        #pragma unroll
        for (int i = 0; i < 8; i++) {
            e[i] = Et[i * 32 + lane];
            pf += wh[i] * tanh_fast(S[i] + bsr[i]);
            pa += wh[i] * tanh_fast(e[i] + bsr[i]);
        }
        #pragma unroll
        for (int o = 16; o > 0; o >>= 1) {
            pf += __shfl_xor_sync(0xffffffffu, pf, o);
            pa += __shfl_xor_sync(0xffffffffu, pa, o);
        }
        // softmax([gf, ga]); bh[l] adds to both logits -> cancels
        float g0 = 1.0f / (1.0f + __expf(pa - pf));
        float g1 = 1.0f - g0;

        #pragma unroll
        for (int i = 0; i < 8; i++) S[i] = g0 * S[i] + g1 * e[i];

        X = g0 * X + g1 * g_dxyz[r * 3 + 0];
        Y = g0 * Y + g1 * g_dxyz[r * 3 + 1];
        Z = g0 * Z + g1 * g_dxyz[r * 3 + 2];
        cx = g0 * cx + g1 * px;          // rois = previous pred
        cy = g0 * cy + g1 * py;
        cz = g0 * cz + g1 * pz;
        px = (X + bxl) * s0 + cx;
        py = (Y + byl) * s0 + cy;
        pz = (Z + bzl) * s2 + cz;
        if (lane == 0) {
            out[r * 3 + 0] = px;
            out[r * 3 + 1] = py;
            out[r * 3 + 2] = pz;
        }
    }
}

// ---------------- launch ----------------
extern "C" void kernel_launch(void* const* d_in, const int* in_sizes, int n_in,
                              void* d_out, int out_size) {
    const float* emb  = (const float*)d_in[0];   // (8, 4096, 512)
    const float* rois = (const float*)d_in[1];   // (1, 4096, 3)
    const float* Wx   = (const float*)d_in[2];
    const float* bx   = (const float*)d_in[3];
    const float* Wy   = (const float*)d_in[4];
    const float* by   = (const float*)d_in[5];
    const float* Wz   = (const float*)d_in[6];
    const float* bz   = (const float*)d_in[7];
    const float* Ws   = (const float*)d_in[8];   // (512, 256)
    const float* bs   = (const float*)d_in[9];   // (256,)
    const float* Wh   = (const float*)d_in[10];  // (4096, 256)
    // d_in[11] = bh: cancels inside the 2-way softmax, unused.
    float* out = (float*)d_out;                  // (8, 4096, 3)

    k_convert_ws<<<512, 256>>>(Ws);
    k_gemm_e<<<dim3(M_TOT / BM, H_DIM / BN), 256>>>(emb);
    k_dec_dots<<<L_DIM, 256>>>(emb, Wx, Wy, Wz);
    k_seq<<<L_DIM / 8, 256>>>(rois, Wh, bs, bx, by, bz, out);
}

// round 3
// speedup vs baseline: 1.8583x; 1.8583x over previous
#include <cuda_runtime.h>
#include <cuda_bf16.h>
#include <cstdint>

#define T_ITER 8
#define L_DIM  4096
#define D_DIM  512
#define H_DIM  256
#define M_TOT  (T_ITER * L_DIM)   // 32768 rows

// ---------------- scratch ----------------
__device__ float          g_E[(size_t)M_TOT * H_DIM];    // emb @ Ws (no bias), 32 MB
__device__ float          g_dxyz[(size_t)M_TOT * 3];     // dec row dots
__device__ float          g_pa[2 * M_TOT];               // gate logit (emb side), 2 col-halves
__device__ __nv_bfloat16  g_BT[H_DIM * D_DIM];           // Ws^T bf16, [n][k]

__device__ __forceinline__ float tanhap(float x) {
    float y;
    asm("tanh.approx.f32 %0, %1;" : "=f"(y) : "f"(x));
    return y;
}

// ---------------- kernel 0: Ws -> bf16 transposed ----------------
__global__ void k_convert_ws(const float* __restrict__ Ws) {
    int idx = blockIdx.x * blockDim.x + threadIdx.x;  // 512*256
    float v = Ws[idx];
    int k = idx >> 8, n = idx & 255;
    g_BT[n * D_DIM + k] = __float2bfloat16(v);
}

// ---------------- kernel 1: E = emb @ Ws (bf16 1-term) + fused dots + fused pa ----------
#define BM 128
#define BN 128
#define BK 32
#define SAS 40

__device__ __forceinline__ void mma_bf16(float c[4],
                                         uint32_t a0, uint32_t a1, uint32_t a2, uint32_t a3,
                                         uint32_t b0, uint32_t b1) {
    asm volatile(
        "mma.sync.aligned.m16n8k16.row.col.f32.bf16.bf16.f32 "
        "{%0,%1,%2,%3}, {%4,%5,%6,%7}, {%8,%9}, {%0,%1,%2,%3};\n"
        : "+f"(c[0]), "+f"(c[1]), "+f"(c[2]), "+f"(c[3])
        : "r"(a0), "r"(a1), "r"(a2), "r"(a3), "r"(b0), "r"(b1));
}

__global__ void __launch_bounds__(256, 2) k_gemm_e(const float* __restrict__ A,
                                                   const float* __restrict__ Wx,
                                                   const float* __restrict__ Wy,
                                                   const float* __restrict__ Wz,
                                                   const float* __restrict__ Wh,
                                                   const float* __restrict__ bs) {
    __shared__ __align__(16) __nv_bfloat16 sA[BM * SAS];
    __shared__ __align__(16) __nv_bfloat16 sB[BN * SAS];
    __shared__ float spa[BM][4];

    const int tid  = threadIdx.x;
    const int lane = tid & 31, wid = tid >> 5;
    const int grp  = lane >> 2, tig = lane & 3;
    const int m0   = blockIdx.x * BM, n0 = blockIdx.y * BN;
    const int wm   = (wid & 1) * 64;
    const int wn   = (wid >> 1) * 32;
    const bool doDots = (blockIdx.y == 0);
    const int  lbase  = (blockIdx.x & 31) * BM;   // l index of row 0 in this tile

    const int arow = tid >> 3;
    const int af4  = (tid & 7) * 4;
    const int bn   = tid >> 1;
    const int bk   = (tid & 1) * 16;

    float acc[4][4][4];
    #pragma unroll
    for (int i = 0; i < 4; i++)
        #pragma unroll
        for (int j = 0; j < 4; j++)
            #pragma unroll
            for (int r = 0; r < 4; r++) acc[i][j][r] = 0.f;

    float dxa[4], dya[4], dza[4];
    #pragma unroll
    for (int p = 0; p < 4; p++) { dxa[p] = 0.f; dya[p] = 0.f; dza[p] = 0.f; }

    float4 aReg[4];
    uint4  bReg0, bReg1;

    const float* Abase = A + (size_t)m0 * D_DIM;
    const __nv_bfloat16* Bp = g_BT + (size_t)(n0 + bn) * D_DIM + bk;

    #pragma unroll
    for (int p = 0; p < 4; p++)
        aReg[p] = *(const float4*)(Abase + (size_t)(p * 32 + arow) * D_DIM + af4);
    bReg0 = *(const uint4*)(Bp);  bReg1 = *(const uint4*)(Bp + 8);

    for (int kt = 0; kt < D_DIM / BK; kt++) {
        // stage -> smem, convert to bf16, and (by==0) accumulate dec dots
        #pragma unroll
        for (int p = 0; p < 4; p++) {
            float f[4] = {aReg[p].x, aReg[p].y, aReg[p].z, aReg[p].w};
            if (doDots) {
                size_t woff = (size_t)(lbase + p * 32 + arow) * D_DIM + kt * BK + af4;
                float4 wx4 = *(const float4*)(Wx + woff);
                float4 wy4 = *(const float4*)(Wy + woff);
                float4 wz4 = *(const float4*)(Wz + woff);
                dxa[p] += f[0]*wx4.x + f[1]*wx4.y + f[2]*wx4.z + f[3]*wx4.w;
                dya[p] += f[0]*wy4.x + f[1]*wy4.y + f[2]*wy4.z + f[3]*wy4.w;
                dza[p] += f[0]*wz4.x + f[1]*wz4.y + f[2]*wz4.z + f[3]*wz4.w;
            }
            unsigned short h[4];
            #pragma unroll
            for (int q = 0; q < 4; q++)
                h[q] = __bfloat16_as_ushort(__float2bfloat16(f[q]));
            int off = (p * 32 + arow) * SAS + af4;
            *(uint2*)&sA[off] = make_uint2((uint32_t)h[0] | ((uint32_t)h[1] << 16),
                                           (uint32_t)h[2] | ((uint32_t)h[3] << 16));
        }
        {
            int off = bn * SAS + bk;
            *(uint4*)&sB[off]     = bReg0;
            *(uint4*)&sB[off + 8] = bReg1;
        }
        __syncthreads();

        if (kt + 1 < D_DIM / BK) {
            const float* An = Abase + (kt + 1) * BK;
            #pragma unroll
            for (int p = 0; p < 4; p++)
                aReg[p] = *(const float4*)(An + (size_t)(p * 32 + arow) * D_DIM + af4);
            const __nv_bfloat16* B2 = Bp + (kt + 1) * BK;
            bReg0 = *(const uint4*)(B2);  bReg1 = *(const uint4*)(B2 + 8);
        }

        #pragma unroll
        for (int ks = 0; ks < 2; ks++) {
            uint32_t bf[4][2];
            #pragma unroll
            for (int ni = 0; ni < 4; ni++) {
                int r = wn + ni * 8 + grp;
                int c = ks * 16 + 2 * tig;
                bf[ni][0] = *(const uint32_t*)&sB[r * SAS + c];
                bf[ni][1] = *(const uint32_t*)&sB[r * SAS + c + 8];
            }
            #pragma unroll
            for (int mi = 0; mi < 4; mi++) {
                int r = wm + mi * 16 + grp;
                int c = ks * 16 + 2 * tig;
                uint32_t a0 = *(const uint32_t*)&sA[r * SAS + c];
                uint32_t a1 = *(const uint32_t*)&sA[(r + 8) * SAS + c];
                uint32_t a2 = *(const uint32_t*)&sA[r * SAS + c + 8];
                uint32_t a3 = *(const uint32_t*)&sA[(r + 8) * SAS + c + 8];
                #pragma unroll
                for (int ni = 0; ni < 4; ni++)
                    mma_bf16(acc[mi][ni], a0, a1, a2, a3, bf[ni][0], bf[ni][1]);
            }
        }
        __syncthreads();
    }

    // ---- epilogue: store E ----
    #pragma unroll
    for (int mi = 0; mi < 4; mi++) {
        #pragma unroll
        for (int ni = 0; ni < 4; ni++) {
            int row = m0 + wm + mi * 16 + grp;
            int col = n0 + wn + ni * 8 + 2 * tig;
            *(float2*)&g_E[(size_t)row * H_DIM + col]       = make_float2(acc[mi][ni][0], acc[mi][ni][1]);
            *(float2*)&g_E[(size_t)(row + 8) * H_DIM + col] = make_float2(acc[mi][ni][2], acc[mi][ni][3]);
        }
    }

    // ---- epilogue: dec dots (by==0): reduce over 8-thread octets ----
    if (doDots) {
        #pragma unroll
        for (int p = 0; p < 4; p++) {
            float sx = dxa[p], sy = dya[p], sz = dza[p];
            #pragma unroll
            for (int o = 4; o > 0; o >>= 1) {
                sx += __shfl_xor_sync(0xffffffffu, sx, o);
                sy += __shfl_xor_sync(0xffffffffu, sy, o);
                sz += __shfl_xor_sync(0xffffffffu, sz, o);
            }
            if ((lane & 7) == 0) {
                size_t row = (size_t)m0 + p * 32 + arow;
                g_dxyz[row * 3 + 0] = sx;
                g_dxyz[row * 3 + 1] = sy;
                g_dxyz[row * 3 + 2] = sz;
            }
        }
    }

    // ---- epilogue: pa partials (t>=1 rows only) ----
    bool doPa = (blockIdx.x >= 32);
    if (doPa) {
        float rowpart[8];
        #pragma unroll
        for (int j = 0; j < 8; j++) rowpart[j] = 0.f;
        #pragma unroll
        for (int ni = 0; ni < 4; ni++) {
            int col = n0 + wn + ni * 8 + 2 * tig;
            float2 bsv = *(const float2*)&bs[col];
            #pragma unroll
            for (int mi = 0; mi < 4; mi++) {
                int l0 = lbase + wm + mi * 16 + grp;
                float2 w0 = *(const float2*)&Wh[(size_t)l0 * H_DIM + col];
                float2 w1 = *(const float2*)&Wh[(size_t)(l0 + 8) * H_DIM + col];
                rowpart[mi*2]   += w0.x * tanhap(acc[mi][ni][0] + bsv.x)
                                 + w0.y * tanhap(acc[mi][ni][1] + bsv.y);
                rowpart[mi*2+1] += w1.x * tanhap(acc[mi][ni][2] + bsv.x)
                                 + w1.y * tanhap(acc[mi][ni][3] + bsv.y);
            }
        }
        #pragma unroll
        for (int j = 0; j < 8; j++) {
            rowpart[j] += __shfl_xor_sync(0xffffffffu, rowpart[j], 1);
            rowpart[j] += __shfl_xor_sync(0xffffffffu, rowpart[j], 2);
        }
        if (tig == 0) {
            #pragma unroll
            for (int mi = 0; mi < 4; mi++) {
                spa[wm + mi * 16 + grp][wid >> 1]     = rowpart[mi*2];
                spa[wm + mi * 16 + grp + 8][wid >> 1] = rowpart[mi*2+1];
            }
        }
    }
    __syncthreads();
    if (doPa && tid < BM) {
        float s = ((spa[tid][0] + spa[tid][1]) + (spa[tid][2] + spa[tid][3]));
        g_pa[(size_t)blockIdx.y * M_TOT + m0 + tid] = s;
    }
}

// ---------------- kernel 2: fused sequential recurrence ----------------
__global__ void __launch_bounds__(256) k_seq(const float* __restrict__ rois,
                                             const float* __restrict__ Wh,
                                             const float* __restrict__ bs,
                                             const float* __restrict__ bx,
                                             const float* __restrict__ by,
                                             const float* __restrict__ bz,
                                             float* __restrict__ out) {
    int wid = threadIdx.x >> 5, lane = threadIdx.x & 31;
    int l = blockIdx.x * 8 + wid;

    float wh[8], bsr[8], S[8];
    #pragma unroll
    for (int i = 0; i < 8; i++) {
        int j = i * 32 + lane;
        wh[i]  = Wh[(size_t)l * H_DIM + j];
        bsr[i] = bs[j];
        S[i]   = g_E[(size_t)l * H_DIM + j];
    }

    // preload all steps upfront (max MLP; nothing on the chain depends on these loads)
    float e[7][8], dxs[7], dys[7], dzs[7], pas[7];
    #pragma unroll
    for (int t = 0; t < 7; t++) {
        size_t r = (size_t)(t + 1) * L_DIM + l;
        #pragma unroll
        for (int i = 0; i < 8; i++)
            e[t][i] = g_E[r * H_DIM + i * 32 + lane];
        dxs[t] = g_dxyz[r * 3 + 0];
        dys[t] = g_dxyz[r * 3 + 1];
        dzs[t] = g_dxyz[r * 3 + 2];
        pas[t] = g_pa[r] + g_pa[M_TOT + r];
    }

    float X = g_dxyz[(size_t)l * 3 + 0];
    float Y = g_dxyz[(size_t)l * 3 + 1];
    float Z = g_dxyz[(size_t)l * 3 + 2];
    float cx = rois[(size_t)l * 3 + 0];
    float cy = rois[(size_t)l * 3 + 1];
    float cz = rois[(size_t)l * 3 + 2];
    float bxl = bx[l], byl = by[l], bzl = bz[l];
    const float s0 = 1.0f / 767.0f, s2 = 1.0f / 575.0f;

    float px = (X + bxl) * s0 + cx;
    float py = (Y + byl) * s0 + cy;
    float pz = (Z + bzl) * s2 + cz;
    if (lane == 0) {
        out[(size_t)l * 3 + 0] = px;
        out[(size_t)l * 3 + 1] = py;
        out[(size_t)l * 3 + 2] = pz;
    }

    #pragma unroll
    for (int t = 0; t < 7; t++) {
        // pf = sum_j wh_j * tanh(S_j + bs_j)  (tree sum, then warp reduce)
        float q[8];
        #pragma unroll
        for (int i = 0; i < 8; i++)
            q[i] = wh[i] * tanhap(S[i] + bsr[i]);
        float pf = ((q[0]+q[1]) + (q[2]+q[3])) + ((q[4]+q[5]) + (q[6]+q[7]));
        #pragma unroll
        for (int o = 16; o > 0; o >>= 1)
            pf += __shfl_xor_sync(0xffffffffu, pf, o);

        // g0 = sigmoid(pf - pa) = 0.5 + 0.5*tanh((pf - pa)/2)
        float g0 = fmaf(0.5f, tanhap(0.5f * (pf - pas[t])), 0.5f);
        float g1 = 1.0f - g0;

        #pragma unroll
        for (int i = 0; i < 8; i++) S[i] = g0 * S[i] + g1 * e[t][i];

        X = g0 * X + g1 * dxs[t];
        Y = g0 * Y + g1 * dys[t];
        Z = g0 * Z + g1 * dzs[t];
        cx = g0 * cx + g1 * px;
        cy = g0 * cy + g1 * py;
        cz = g0 * cz + g1 * pz;
        px = (X + bxl) * s0 + cx;
        py = (Y + byl) * s0 + cy;
        pz = (Z + bzl) * s2 + cz;
        if (lane == 0) {
            size_t r = (size_t)(t + 1) * L_DIM + l;
            out[r * 3 + 0] = px;
            out[r * 3 + 1] = py;
            out[r * 3 + 2] = pz;
        }
    }
}

// ---------------- launch ----------------
extern "C" void kernel_launch(void* const* d_in, const int* in_sizes, int n_in,
                              void* d_out, int out_size) {
    const float* emb  = (const float*)d_in[0];
    const float* rois = (const float*)d_in[1];
    const float* Wx   = (const float*)d_in[2];
    const float* bx   = (const float*)d_in[3];
    const float* Wy   = (const float*)d_in[4];
    const float* by   = (const float*)d_in[5];
    const float* Wz   = (const float*)d_in[6];
    const float* bz   = (const float*)d_in[7];
    const float* Ws   = (const float*)d_in[8];
    const float* bs   = (const float*)d_in[9];
    const float* Wh   = (const float*)d_in[10];
    // d_in[11] = bh: cancels in the 2-way softmax.
    float* out = (float*)d_out;

    k_convert_ws<<<512, 256>>>(Ws);
    k_gemm_e<<<dim3(M_TOT / BM, H_DIM / BN), 256>>>(emb, Wx, Wy, Wz, Wh, bs);
    k_seq<<<L_DIM / 8, 256>>>(rois, Wh, bs, bx, by, bz, out);
}